// round 3
// baseline (speedup 1.0000x reference)
#include <cuda_runtime.h>
#include <math.h>

#define BSZ   4
#define CCH   128
#define NPT   2000
#define KNNK  9
#define NHEAD 4
#define HD    32
#define BN_EPS 1e-5f

// ---------------- scratch ------------------------------------------------
__device__ float g_w1sb[2*CCH*CCH];   // [w1a+w1b ; w1b] (256x128)
__device__ float g_wkv [2*CCH*CCH];   // [wk ; wv]
__device__ float g_bkv [2*CCH];
__device__ float g_eb  [2*CCH];       // stacked epilogue for uvt: [b1;0]
__device__ float g_eg  [2*CCH];       //                            [g1;g1]
__device__ float g_ebe [2*CCH];       //                            [be1;0]
__device__ float g_gram[(size_t)BSZ*NPT*NPT];
__device__ float g_xx[BSZ*NPT];
__device__ int   g_idx[BSZ*NPT*KNNK];
__device__ float g_uvt[(size_t)BSZ*NPT*2*CCH];   // [b][n][256] : u3t | v3t
__device__ float g_h2 [(size_t)BSZ*CCH*NPT*KNNK];
__device__ float g_agg[BSZ*CCH*NPT];
__device__ float g_q  [BSZ*CCH*NPT];
__device__ float g_kv [BSZ*2*CCH*NPT];
__device__ float g_add[BSZ*CCH*NPT];
__device__ float g_cat[BSZ*2*CCH*NPT];
__device__ float g_hc [BSZ*2*CCH*NPT];

// ---------------- generic tiled SGEMM (reg-prefetch double buffer) --------
#define TM 128
#define TN 128
#define TK 8

template<bool TA, bool TB, bool EPIN>
__global__ void __launch_bounds__(256) gemm_k(
    const float* __restrict__ A, const float* __restrict__ B, float* __restrict__ Cm,
    int M, int Nc, int Kc, int lda, int ldb, int ldc,
    long long sA, long long sB, long long sC,
    float alpha,
    const float* __restrict__ bias,
    const float* __restrict__ gamma, const float* __restrict__ beta,
    int relu,
    const float* __restrict__ resid, long long sR, int ldr)
{
    int bz = blockIdx.z;
    A  += (long long)bz * sA;
    B  += (long long)bz * sB;
    Cm += (long long)bz * sC;
    if (resid) resid += (long long)bz * sR;

    __shared__ float As[TK][TM];
    __shared__ float Bs[TK][TN];

    int m0 = blockIdx.y * TM;
    int n0 = blockIdx.x * TN;
    int tid = threadIdx.x;
    int tx = tid % 16, ty = tid / 16;

    float acc[8][8];
    #pragma unroll
    for (int i=0;i<8;i++)
        #pragma unroll
        for (int j=0;j<8;j++) acc[i][j] = 0.f;

    float ra[4], rb[4];

#define GK_LOAD(KT0) {                                                     \
    _Pragma("unroll")                                                      \
    for (int it=0; it<4; it++){                                            \
        int e = tid + it*256; int m_,k_;                                   \
        if (TA){ m_ = e % TM; k_ = e / TM; } else { k_ = e % TK; m_ = e / TK; } \
        int gm = m0+m_, gk = (KT0)+k_;                                     \
        ra[it] = (gm<M && gk<Kc) ? (TA ? A[(long long)gk*lda+gm]           \
                                       : A[(long long)gm*lda+gk]) : 0.f;   \
    }                                                                      \
    _Pragma("unroll")                                                      \
    for (int it=0; it<4; it++){                                            \
        int e = tid + it*256; int n_,k_;                                   \
        if (TB){ k_ = e % TK; n_ = e / TK; } else { n_ = e % TN; k_ = e / TN; } \
        int gn = n0+n_, gk = (KT0)+k_;                                     \
        rb[it] = (gn<Nc && gk<Kc) ? (TB ? B[(long long)gn*ldb+gk]          \
                                        : B[(long long)gk*ldb+gn]) : 0.f;  \
    } }

#define GK_STORE() {                                                       \
    _Pragma("unroll")                                                      \
    for (int it=0; it<4; it++){                                            \
        int e = tid + it*256; int m_,k_;                                   \
        if (TA){ m_ = e % TM; k_ = e / TM; } else { k_ = e % TK; m_ = e / TK; } \
        As[k_][m_] = ra[it];                                               \
    }                                                                      \
    _Pragma("unroll")                                                      \
    for (int it=0; it<4; it++){                                            \
        int e = tid + it*256; int n_,k_;                                   \
        if (TB){ k_ = e % TK; n_ = e / TK; } else { n_ = e % TN; k_ = e / TN; } \
        Bs[k_][n_] = rb[it];                                               \
    } }

#define GK_COMPUTE() {                                                     \
    _Pragma("unroll")                                                      \
    for (int kk=0; kk<TK; kk++){                                           \
        float4 a0 = *(const float4*)&As[kk][ty*8];                         \
        float4 a1 = *(const float4*)&As[kk][ty*8+4];                       \
        float4 b0 = *(const float4*)&Bs[kk][tx*8];                         \
        float4 b1 = *(const float4*)&Bs[kk][tx*8+4];                       \
        float av[8] = {a0.x,a0.y,a0.z,a0.w,a1.x,a1.y,a1.z,a1.w};           \
        float bv8[8] = {b0.x,b0.y,b0.z,b0.w,b1.x,b1.y,b1.z,b1.w};          \
        _Pragma("unroll")                                                  \
        for (int i=0;i<8;i++)                                              \
            _Pragma("unroll")                                              \
            for (int j=0;j<8;j++) acc[i][j] += av[i]*bv8[j];               \
    } }

    GK_LOAD(0);
    GK_STORE();
    for (int kt = TK; kt < Kc; kt += TK) {
        __syncthreads();
        GK_LOAD(kt);
        GK_COMPUTE();
        __syncthreads();
        GK_STORE();
    }
    __syncthreads();
    GK_COMPUTE();

    const float invs = rsqrtf(1.0f + BN_EPS);
    #pragma unroll
    for (int i=0;i<8;i++) {
        int gm = m0 + ty*8 + i;
        if (gm >= M) continue;
        float bi = 0.f, ga = 1.f, be = 0.f;
        if (!EPIN) {
            if (bias)  bi = bias[gm];
            if (gamma) { ga = gamma[gm]*invs; be = beta[gm]; }
        }
        #pragma unroll
        for (int j=0;j<8;j++) {
            int gn = n0 + tx*8 + j;
            if (gn >= Nc) continue;
            if (EPIN) {
                if (bias)  bi = bias[gn];
                if (gamma) { ga = gamma[gn]*invs; be = beta[gn]; }
            }
            float r = acc[i][j]*alpha + bi;
            if (gamma) r = r*ga + be;
            if (relu)  r = fmaxf(r, 0.f);
            if (resid) r += resid[(long long)gm*ldr + gn];
            Cm[(long long)gm*ldc + gn] = r;
        }
    }
#undef GK_LOAD
#undef GK_STORE
#undef GK_COMPUTE
}

// ---------------- edge-conv GEMM: B built on the fly -----------------------
// out[b][o][col] = relu? bn( sum_c W[o][c] * relu(u3t[n][c]-v3t[j][c]) + b2 )
__global__ void __launch_bounds__(256) gemm_edge(
    const float* __restrict__ W,     // [128][128]
    const float* __restrict__ uvt,   // [B][N][256]
    const int* __restrict__ idx,
    const float* __restrict__ bias, const float* __restrict__ gamma,
    const float* __restrict__ beta,
    float* __restrict__ out)         // [B][128][18000]
{
    extern __shared__ float sm[];
    float* Asm = sm;                 // [128][128]  (m-major)
    float* Bsf = Asm + CCH*CCH;      // [TK][TN]
    int*  ncol = (int*)(Bsf + TK*TN);
    int*  jcol = ncol + TN;

    int b  = blockIdx.z;
    int n0 = blockIdx.x * TN;
    int tid = threadIdx.x;
    const float* ub = uvt + (long long)b*NPT*2*CCH;
    const int NCOLS = NPT*KNNK;

    // A resident (coalesced float4 loads, contiguous STS)
    #pragma unroll
    for (int it=0; it<16; it++){
        int e4 = tid + it*256;           // 4096 float4s
        float4 w4 = *(const float4*)(W + e4*4);
        *(float4*)(Asm + e4*4) = w4;
    }
    // column meta
    if (tid < TN){
        int col = n0 + tid;
        if (col < NCOLS){
            int n = col / KNNK;
            int kk = col - n*KNNK;
            ncol[tid] = n;
            jcol[tid] = idx[(b*NPT+n)*KNNK + kk];
        } else { ncol[tid] = -1; jcol[tid] = 0; }
    }
    __syncthreads();

    int cc = tid & 127;
    int kh = tid >> 7;                  // 0..1 -> k rows kh*4..kh*4+3
    int nc = ncol[cc], jc = jcol[cc];
    bool valid = (nc >= 0);
    const float* up = ub + (long long)(valid ? nc : 0)*2*CCH;
    const float* vp = ub + (long long)(valid ? jc : 0)*2*CCH + CCH;

    int tx = tid & 15, ty = tid >> 4;
    float acc[8][8];
    #pragma unroll
    for (int i=0;i<8;i++)
        #pragma unroll
        for (int j=0;j<8;j++) acc[i][j] = 0.f;

    float4 rbv;

#define GE_LOAD(KT0) {                                                \
    float4 u4 = *(const float4*)(up + (KT0) + kh*4);                  \
    float4 v4 = *(const float4*)(vp + (KT0) + kh*4);                  \
    rbv.x = valid ? fmaxf(u4.x - v4.x, 0.f) : 0.f;                    \
    rbv.y = valid ? fmaxf(u4.y - v4.y, 0.f) : 0.f;                    \
    rbv.z = valid ? fmaxf(u4.z - v4.z, 0.f) : 0.f;                    \
    rbv.w = valid ? fmaxf(u4.w - v4.w, 0.f) : 0.f; }

#define GE_STORE() {                                                  \
    Bsf[(kh*4+0)*TN + cc] = rbv.x;                                    \
    Bsf[(kh*4+1)*TN + cc] = rbv.y;                                    \
    Bsf[(kh*4+2)*TN + cc] = rbv.z;                                    \
    Bsf[(kh*4+3)*TN + cc] = rbv.w; }

#define GE_COMPUTE(KTA) {                                             \
    _Pragma("unroll")                                                 \
    for (int kk4=0; kk4<TK; kk4+=4){                                  \
        float4 av4[8];                                                \
        _Pragma("unroll")                                             \
        for (int i=0;i<8;i++)                                         \
            av4[i] = *(const float4*)&Asm[(ty*8+i)*CCH + (KTA) + kk4];\
        _Pragma("unroll")                                             \
        for (int q=0;q<4;q++){                                        \
            int kk = kk4 + q;                                         \
            float4 b0 = *(const float4*)&Bsf[kk*TN + tx*8];           \
            float4 b1 = *(const float4*)&Bsf[kk*TN + tx*8+4];         \
            float bv8[8] = {b0.x,b0.y,b0.z,b0.w,b1.x,b1.y,b1.z,b1.w}; \
            _Pragma("unroll")                                         \
            for (int i=0;i<8;i++){                                    \
                float a = (&av4[i].x)[q];                             \
                _Pragma("unroll")                                     \
                for (int j=0;j<8;j++) acc[i][j] += a*bv8[j];          \
            }                                                         \
        }                                                             \
    } }

    GE_LOAD(0);
    GE_STORE();
    for (int kt = TK; kt < CCH; kt += TK){
        __syncthreads();
        GE_LOAD(kt);
        GE_COMPUTE(kt - TK);
        __syncthreads();
        GE_STORE();
    }
    __syncthreads();
    GE_COMPUTE(CCH - TK);

    const float invs = rsqrtf(1.0f + BN_EPS);
    float* ob = out + (long long)b*CCH*NCOLS;
    #pragma unroll
    for (int i=0;i<8;i++){
        int gm = ty*8 + i;
        float bi = bias[gm];
        float ga = gamma[gm]*invs;
        float be = beta[gm];
        #pragma unroll
        for (int j=0;j<8;j++){
            int gn = n0 + tx*8 + j;
            if (gn >= NCOLS) continue;
            float r = (acc[i][j] + bi)*ga + be;
            ob[(long long)gm*NCOLS + gn] = fmaxf(r, 0.f);
        }
    }
#undef GE_LOAD
#undef GE_STORE
#undef GE_COMPUTE
}

// ---------------- prep ------------------------------------------------------
__global__ void prep_kernel(const float* __restrict__ w1,
                            const float* __restrict__ wk, const float* __restrict__ wv,
                            const float* __restrict__ bk, const float* __restrict__ bv,
                            const float* __restrict__ b1, const float* __restrict__ g1,
                            const float* __restrict__ be1,
                            float* __restrict__ w1sb, float* __restrict__ wkv,
                            float* __restrict__ bkv,
                            float* __restrict__ eb, float* __restrict__ eg,
                            float* __restrict__ ebe)
{
    int i = blockIdx.x*blockDim.x + threadIdx.x;
    if (i < CCH*CCH) {
        int o = i / CCH, c = i % CCH;
        float a  = w1[o*2*CCH + c];
        float bb = w1[o*2*CCH + CCH + c];
        w1sb[i] = a + bb;
        w1sb[CCH*CCH + i] = bb;
        wkv[i] = wk[i];
        wkv[CCH*CCH + i] = wv[i];
    }
    if (i < CCH) {
        bkv[i] = bk[i];        bkv[CCH+i] = bv[i];
        eb[i]  = b1[i];        eb[CCH+i]  = 0.f;
        eg[i]  = g1[i];        eg[CCH+i]  = g1[i];
        ebe[i] = be1[i];       ebe[CCH+i] = 0.f;
    }
}

__global__ void xx_kernel(const float* __restrict__ gram, float* __restrict__ xx)
{
    int i = blockIdx.x*blockDim.x + threadIdx.x;
    if (i < BSZ*NPT) {
        int b = i / NPT, n = i % NPT;
        xx[i] = gram[((long long)(b*NPT+n))*NPT + n];
    }
}

// ---------------- topk: lane sort-8 + warp k-way merge -----------------------
__global__ void __launch_bounds__(256) topk_kernel(const float* __restrict__ gram,
                                                   const float* __restrict__ xx,
                                                   int* __restrict__ idx)
{
    int n = blockIdx.x, b = blockIdx.y;
    const float* row = gram + ((long long)(b*NPT+n))*NPT;
    const float* xb  = xx + b*NPT;
    int tid = threadIdx.x, w = tid >> 5, l = tid & 31;

    float v[8]; int id[8];
    #pragma unroll
    for (int j=0;j<8;j++){
        int m = w*256 + j*32 + l;
        bool ok = m < NPT;
        v[j]  = ok ? (2.f*row[m] - xb[m]) : -INFINITY;
        id[j] = ok ? m : 0x7fffffff;
    }
    // sort descending (tie: lower idx first), odd-even merge network (19)
#define CSWP(a,bb) { bool sw = (v[a]<v[bb]) || (v[a]==v[bb] && id[a]>id[bb]); \
    float tv = sw?v[bb]:v[a]; float uv2 = sw?v[a]:v[bb]; v[a]=tv; v[bb]=uv2;   \
    int ti = sw?id[bb]:id[a]; int ui = sw?id[a]:id[bb]; id[a]=ti; id[bb]=ui; }
    CSWP(0,1) CSWP(2,3) CSWP(4,5) CSWP(6,7)
    CSWP(0,2) CSWP(1,3) CSWP(4,6) CSWP(5,7)
    CSWP(1,2) CSWP(5,6)
    CSWP(0,4) CSWP(1,5) CSWP(2,6) CSWP(3,7)
    CSWP(2,4) CSWP(3,5)
    CSWP(1,2) CSWP(3,4) CSWP(5,6)
#undef CSWP

    __shared__ float wv[8][12];
    __shared__ int   wi[8][12];

    float hv = v[0]; int hi = id[0];
    #pragma unroll
    for (int t=0;t<KNNK;t++){
        float bvv = hv; int bii = hi;
        #pragma unroll
        for (int s=16; s>0; s>>=1){
            float ov = __shfl_xor_sync(0xffffffffu, bvv, s);
            int   oi = __shfl_xor_sync(0xffffffffu, bii, s);
            if (ov > bvv || (ov == bvv && oi < bii)) { bvv = ov; bii = oi; }
        }
        if (l == 0) { wv[w][t] = bvv; wi[w][t] = bii; }
        if (hi == bii) {
            #pragma unroll
            for (int j=0;j<7;j++){ v[j]=v[j+1]; id[j]=id[j+1]; }
            v[7] = -INFINITY; id[7] = 0x7fffffff;
            hv = v[0]; hi = id[0];
        }
    }
    __syncthreads();

    if (w == 0){
        int ptr = 0;
        float hv2 = (l < 8) ? wv[l][0] : -INFINITY;
        int   hi2 = (l < 8) ? wi[l][0] : 0x7fffffff;
        int* outp = idx + (b*NPT+n)*KNNK;
        #pragma unroll
        for (int t=0;t<KNNK;t++){
            float bvv = hv2; int bii = hi2;
            #pragma unroll
            for (int s=16; s>0; s>>=1){
                float ov = __shfl_xor_sync(0xffffffffu, bvv, s);
                int   oi = __shfl_xor_sync(0xffffffffu, bii, s);
                if (ov > bvv || (ov == bvv && oi < bii)) { bvv = ov; bii = oi; }
            }
            if (l == 0) outp[t] = bii;
            if (hi2 == bii){
                ptr++;
                hv2 = (ptr < KNNK && l < 8) ? wv[l][ptr] : -INFINITY;
                hi2 = (ptr < KNNK && l < 8) ? wi[l][ptr] : 0x7fffffff;
            }
        }
    }
}

// agg[b,c,n] = max_k h2[...]; also writes top half of cat
__global__ void maxk_kernel(const float* __restrict__ h2,
                            float* __restrict__ agg, float* __restrict__ cat)
{
    int i = blockIdx.x*blockDim.x + threadIdx.x;
    if (i >= BSZ*CCH*NPT) return;
    int n = i % NPT;
    int c = (i / NPT) % CCH;
    int b = i / (NPT*CCH);
    const float* p = h2 + ((long long)(b*CCH+c))*NPT*KNNK + (long long)n*KNNK;
    float m = p[0];
    #pragma unroll
    for (int k = 1; k < KNNK; k++) m = fmaxf(m, p[k]);
    agg[i] = m;
    cat[(long long)b*2*CCH*NPT + (long long)c*NPT + n] = m;
}

// ---------------- flash attention: S in registers ----------------------------
#define QT 128
#define KT 64
#define QST_LD 132
#define VT_LD 36

__global__ void __launch_bounds__(256,2) flash_kernel(
    const float* __restrict__ q,   // [B][C][N]
    const float* __restrict__ kv,  // [B][2C][N]
    float* __restrict__ add)       // [B][C][N]
{
    __shared__ float Qst[HD*QST_LD];
    __shared__ float Ks [HD*KT];
    __shared__ float Vt [KT*VT_LD];

    int n0 = blockIdx.x * QT;
    int h  = blockIdx.y;
    int b  = blockIdx.z;
    const float* qh = q  + ((long long)b*CCH   + h*HD)*NPT;
    const float* kh = kv + ((long long)b*2*CCH + h*HD)*NPT;
    const float* vh = kv + ((long long)b*2*CCH + CCH + h*HD)*NPT;
    float* oh = add + ((long long)b*CCH + h*HD)*NPT;

    int tid = threadIdx.x;
    #pragma unroll
    for (int e = tid; e < HD*QT; e += 256) {
        int d = e >> 7, r = e & 127;
        int n = n0 + r;
        Qst[d*QST_LD + r] = (n < NPT) ? qh[d*NPT + n] : 0.f;
    }

    int r2 = tid >> 2;          // 0..63, owns rows 2*r2, 2*r2+1
    int colq = tid & 3;         // 0..3, owns cols colq*16 .. +15
    int row0 = 2*r2;

    float O0[HD], O1[HD];
    #pragma unroll
    for (int d=0; d<HD; d++){ O0[d]=0.f; O1[d]=0.f; }
    float m0r = -INFINITY, m1r = -INFINITY, l0r = 0.f, l1r = 0.f;

    const float scale = 0.17677669529663689f;
    const int ntiles = (NPT + KT - 1)/KT;

    for (int t = 0; t < ntiles; t++) {
        int mt0 = t*KT;
        __syncthreads();
        #pragma unroll
        for (int e = tid; e < HD*KT; e += 256) {
            int d = e >> 6, c = e & 63;
            int m = mt0 + c;
            Ks[d*KT + c]    = (m < NPT) ? kh[d*NPT + m] : 0.f;
            Vt[c*VT_LD + d] = (m < NPT) ? vh[d*NPT + m] : 0.f;
        }
        __syncthreads();

        float s0[16], s1[16];
        #pragma unroll
        for (int j=0;j<16;j++){ s0[j]=0.f; s1[j]=0.f; }

        #pragma unroll
        for (int kk=0; kk<HD; kk++){
            float2 a2 = *(const float2*)&Qst[kk*QST_LD + row0];
            const float* kp = &Ks[kk*KT + colq*16];
            #pragma unroll
            for (int jj=0; jj<4; jj++){
                float4 b4 = *(const float4*)(kp + jj*4);
                s0[jj*4+0] += a2.x*b4.x; s0[jj*4+1] += a2.x*b4.y;
                s0[jj*4+2] += a2.x*b4.z; s0[jj*4+3] += a2.x*b4.w;
                s1[jj*4+0] += a2.y*b4.x; s1[jj*4+1] += a2.y*b4.y;
                s1[jj*4+2] += a2.y*b4.z; s1[jj*4+3] += a2.y*b4.w;
            }
        }

        int mvalid = NPT - mt0;          // >= KT except last tile
        float lm0 = -INFINITY, lm1 = -INFINITY;
        #pragma unroll
        for (int j=0;j<16;j++){
            int m = colq*16 + j;
            s0[j] *= scale; s1[j] *= scale;
            if (m < mvalid){ lm0 = fmaxf(lm0, s0[j]); lm1 = fmaxf(lm1, s1[j]); }
        }
        lm0 = fmaxf(lm0, __shfl_xor_sync(0xffffffffu, lm0, 1));
        lm0 = fmaxf(lm0, __shfl_xor_sync(0xffffffffu, lm0, 2));
        lm1 = fmaxf(lm1, __shfl_xor_sync(0xffffffffu, lm1, 1));
        lm1 = fmaxf(lm1, __shfl_xor_sync(0xffffffffu, lm1, 2));

        float mn0 = fmaxf(m0r, lm0), mn1 = fmaxf(m1r, lm1);
        float al0 = __expf(m0r - mn0), al1 = __expf(m1r - mn1);
        m0r = mn0; m1r = mn1;

        float ls0 = 0.f, ls1 = 0.f;
        #pragma unroll
        for (int j=0;j<16;j++){
            int m = colq*16 + j;
            float e0 = (m < mvalid) ? __expf(s0[j] - mn0) : 0.f;
            float e1 = (m < mvalid) ? __expf(s1[j] - mn1) : 0.f;
            s0[j] = e0; s1[j] = e1;
            ls0 += e0; ls1 += e1;
        }
        l0r = l0r*al0 + ls0;
        l1r = l1r*al1 + ls1;
        #pragma unroll
        for (int d=0; d<HD; d++){ O0[d] *= al0; O1[d] *= al1; }

        #pragma unroll
        for (int j=0;j<16;j++){
            int m = colq*16 + j;
            const float* vr = &Vt[m*VT_LD];
            float p0 = s0[j], p1 = s1[j];
            #pragma unroll
            for (int d=0; d<HD; d+=4){
                float4 v4 = *(const float4*)&vr[d];
                O0[d]   += p0*v4.x; O0[d+1] += p0*v4.y;
                O0[d+2] += p0*v4.z; O0[d+3] += p0*v4.w;
                O1[d]   += p1*v4.x; O1[d+1] += p1*v4.y;
                O1[d+2] += p1*v4.z; O1[d+3] += p1*v4.w;
            }
        }
    }

    // combine the 4 col-quarters
    l0r += __shfl_xor_sync(0xffffffffu, l0r, 1);
    l0r += __shfl_xor_sync(0xffffffffu, l0r, 2);
    l1r += __shfl_xor_sync(0xffffffffu, l1r, 1);
    l1r += __shfl_xor_sync(0xffffffffu, l1r, 2);
    #pragma unroll
    for (int d=0; d<HD; d++){
        O0[d] += __shfl_xor_sync(0xffffffffu, O0[d], 1);
        O0[d] += __shfl_xor_sync(0xffffffffu, O0[d], 2);
        O1[d] += __shfl_xor_sync(0xffffffffu, O1[d], 1);
        O1[d] += __shfl_xor_sync(0xffffffffu, O1[d], 2);
    }
    if (colq == 0){
        float inv0 = 1.f / l0r, inv1 = 1.f / l1r;
        int n = n0 + row0;
        #pragma unroll
        for (int d=0; d<HD; d++){
            if (n < NPT)     oh[(long long)d*NPT + n]     = O0[d]*inv0;
            if (n+1 < NPT)   oh[(long long)d*NPT + n + 1] = O1[d]*inv1;
        }
    }
}

// ---------------- launch ------------------------------------------------------
static inline dim3 ggrid(int M, int Nc, int batches) {
    return dim3((Nc + TN - 1)/TN, (M + TM - 1)/TM, batches);
}

extern "C" void kernel_launch(void* const* d_in, const int* in_sizes, int n_in,
                              void* d_out, int out_size)
{
    const float* x    = (const float*)d_in[0];
    const float* y    = (const float*)d_in[1];
    const float* dgw1 = (const float*)d_in[2];
    const float* dgb1 = (const float*)d_in[3];
    const float* dgg1 = (const float*)d_in[4];
    const float* dgbe1= (const float*)d_in[5];
    const float* dgw2 = (const float*)d_in[6];
    const float* dgb2 = (const float*)d_in[7];
    const float* dgg2 = (const float*)d_in[8];
    const float* dgbe2= (const float*)d_in[9];
    const float* wq   = (const float*)d_in[10];
    const float* bq   = (const float*)d_in[11];
    const float* wk   = (const float*)d_in[12];
    const float* bk   = (const float*)d_in[13];
    const float* wv   = (const float*)d_in[14];
    const float* bv   = (const float*)d_in[15];
    const float* wmh  = (const float*)d_in[16];
    const float* bmh  = (const float*)d_in[17];
    const float* wc1  = (const float*)d_in[18];
    const float* bc1  = (const float*)d_in[19];
    const float* cg   = (const float*)d_in[20];
    const float* cbe  = (const float*)d_in[21];
    const float* wc2  = (const float*)d_in[22];
    const float* bc2  = (const float*)d_in[23];
    float* out = (float*)d_out;

    float *w1sb,*wkv,*bkv,*eb,*eg,*ebe,*gram,*xx,*uvt,*h2,*agg,*q,*kvb,*add,*cat,*hc;
    int* idx;
    cudaGetSymbolAddress((void**)&w1sb, g_w1sb);
    cudaGetSymbolAddress((void**)&wkv,  g_wkv);
    cudaGetSymbolAddress((void**)&bkv,  g_bkv);
    cudaGetSymbolAddress((void**)&eb,   g_eb);
    cudaGetSymbolAddress((void**)&eg,   g_eg);
    cudaGetSymbolAddress((void**)&ebe,  g_ebe);
    cudaGetSymbolAddress((void**)&gram, g_gram);
    cudaGetSymbolAddress((void**)&xx,   g_xx);
    cudaGetSymbolAddress((void**)&idx,  g_idx);
    cudaGetSymbolAddress((void**)&uvt,  g_uvt);
    cudaGetSymbolAddress((void**)&h2,   g_h2);
    cudaGetSymbolAddress((void**)&agg,  g_agg);
    cudaGetSymbolAddress((void**)&q,    g_q);
    cudaGetSymbolAddress((void**)&kvb,  g_kv);
    cudaGetSymbolAddress((void**)&add,  g_add);
    cudaGetSymbolAddress((void**)&cat,  g_cat);
    cudaGetSymbolAddress((void**)&hc,   g_hc);

    const long long CN  = (long long)CCH*NPT;
    const long long NN  = (long long)NPT*NPT;
    const int NCOLS = NPT*KNNK;
    const int EDGE_SMEM = (CCH*CCH + TK*TN)*4 + 2*TN*4;

    cudaFuncSetAttribute(gemm_edge, cudaFuncAttributeMaxDynamicSharedMemorySize, EDGE_SMEM);

    // 1) prep
    prep_kernel<<<(CCH*CCH+255)/256, 256>>>(dgw1, wk, wv, bk, bv,
                                            dgb1, dgg1, dgbe1,
                                            w1sb, wkv, bkv, eb, eg, ebe);

    // 2) gram[b] = x^T x
    gemm_k<true,false,false><<<ggrid(NPT,NPT,BSZ), 256>>>(
        x, x, gram, NPT, NPT, CCH, NPT, NPT, NPT,
        CN, CN, NN, 1.f, nullptr, nullptr, nullptr, 0, nullptr, 0, 0);

    // 3) diag + top-9
    xx_kernel<<<(BSZ*NPT+255)/256, 256>>>(gram, xx);
    topk_kernel<<<dim3(NPT, BSZ), 256>>>(gram, xx, idx);

    // 4) uvt[b][n][0:256] = ((x^T w1sb^T) + eb)*eg + ebe   (transposed output)
    gemm_k<true,true,true><<<ggrid(NPT,2*CCH,BSZ), 256>>>(
        x, w1sb, uvt, NPT, 2*CCH, CCH, NPT, CCH, 2*CCH,
        CN, 0, (long long)NPT*2*CCH,
        1.f, eb, eg, ebe, 0, nullptr, 0, 0);

    // 5) conv2 with fused edge-feature construction + bn + relu
    {
        dim3 grid((NCOLS + TN - 1)/TN, 1, BSZ);
        gemm_edge<<<grid, 256, EDGE_SMEM>>>(dgw2, uvt, idx, dgb2, dgg2, dgbe2, h2);
    }

    // 6) max over k -> agg (+ top half of cat)
    maxk_kernel<<<(BSZ*CCH*NPT+255)/256, 256>>>(h2, agg, cat);

    // 7) q = wq@agg + bq ; kv = [wk;wv]@y + [bk;bv]
    gemm_k<false,false,false><<<ggrid(CCH,NPT,BSZ), 256>>>(
        wq, agg, q, CCH, NPT, CCH, CCH, NPT, NPT,
        0, CN, CN, 1.f, bq, nullptr, nullptr, 0, nullptr, 0, 0);
    gemm_k<false,false,false><<<ggrid(2*CCH,NPT,BSZ), 256>>>(
        wkv, y, kvb, 2*CCH, NPT, CCH, CCH, NPT, NPT,
        0, CN, 2*CN, 1.f, bkv, nullptr, nullptr, 0, nullptr, 0, 0);

    // 8) fused attention -> add
    {
        dim3 grid((NPT + QT - 1)/QT, NHEAD, BSZ);
        flash_kernel<<<grid, 256>>>(q, kvb, add);
    }

    // 9) mh conv -> bottom half of cat
    gemm_k<false,false,false><<<ggrid(CCH,NPT,BSZ), 256>>>(
        wmh, add, cat + CN, CCH, NPT, CCH, CCH, NPT, NPT,
        0, CN, 2*CN, 1.f, bmh, nullptr, nullptr, 0, nullptr, 0, 0);

    // 10) hc = relu(bn(wc1 @ cat + bc1))
    gemm_k<false,false,false><<<ggrid(2*CCH,NPT,BSZ), 256>>>(
        wc1, cat, hc, 2*CCH, NPT, 2*CCH, 2*CCH, NPT, NPT,
        0, 2*CN, 2*CN, 1.f, bc1, cg, cbe, 1, nullptr, 0, 0);

    // 11) out = agg + wc2 @ hc + bc2
    gemm_k<false,false,false><<<ggrid(CCH,NPT,BSZ), 256>>>(
        wc2, hc, out, CCH, NPT, 2*CCH, 2*CCH, NPT, NPT,
        0, 2*CN, CN, 1.f, bc2, nullptr, nullptr, 0, agg, CN, NPT);
}